// round 2
// baseline (speedup 1.0000x reference)
#include <cuda_runtime.h>
#include <cuda_bf16.h>
#include <cstdint>

// OptionAttentionSum: out[b,o] = (sum_w sum_l [doc[b,l]==opt[b,o,w]] * prob[b,l]) / #nonzero words
//
// NOTE: JAX silently downgrades int64 -> int32 without x64 mode, so the integer
// inputs are int32 buffers (previous round's NaN came from reading them as int64).
//
// Strategy: per-batch CTA builds a 256-slot open-addressing hash table of the <=50
// option words in shared memory, streams the 4096 document positions once with
// ~1.3 probes each, then 10 threads assemble the per-option outputs.

static constexpr int B = 128;
static constexpr int L = 4096;
static constexpr int O = 10;
static constexpr int W = 5;
static constexpr int OW = O * W;          // 50
static constexpr int TSIZE = 256;         // hash table slots (power of 2)
static constexpr int THREADS = 512;
static constexpr int KEMPTY = (int)0x80000000;  // impossible key (values in [0, 50000))

__device__ __forceinline__ unsigned hash_key(int key) {
    return ((unsigned)key * 2654435761u) >> (32 - 8);   // top 8 bits -> [0,256)
}

__global__ __launch_bounds__(THREADS, 1)
void option_attention_sum_kernel(const int* __restrict__ doc_idx,
                                 const float* __restrict__ doc_prob,
                                 const int* __restrict__ options,
                                 float* __restrict__ out) {
    __shared__ int   s_key[TSIZE];
    __shared__ float s_acc[TSIZE];

    const int b   = blockIdx.x;
    const int tid = threadIdx.x;

    // ---- init table ----
    for (int i = tid; i < TSIZE; i += THREADS) {
        s_key[i] = KEMPTY;
        s_acc[i] = 0.0f;
    }
    __syncthreads();

    // ---- insert the (<=50) option words ----
    const int* opt = options + b * OW;
    if (tid < OW) {
        const int key = opt[tid];
        unsigned h = hash_key(key);
        while (true) {
            int old = atomicCAS(&s_key[h], KEMPTY, key);
            if (old == KEMPTY || old == key) break;
            h = (h + 1) & (TSIZE - 1);
        }
    }
    __syncthreads();

    // ---- stream the document: 128-bit loads, 4 keys + 4 probs per iteration ----
    const int4*   di4 = reinterpret_cast<const int4*>(doc_idx + b * L);
    const float4* dp4 = reinterpret_cast<const float4*>(doc_prob + b * L);

    #pragma unroll
    for (int i = tid; i < L / 4; i += THREADS) {
        const int4   d4 = di4[i];
        const float4 p4 = dp4[i];

        const int   dk[4] = {d4.x, d4.y, d4.z, d4.w};
        const float pp[4] = {p4.x, p4.y, p4.z, p4.w};

        #pragma unroll
        for (int j = 0; j < 4; j++) {
            const int d = dk[j];
            unsigned h = hash_key(d);
            while (true) {
                const int k = s_key[h];
                if (k == KEMPTY) break;                       // miss (common case)
                if (k == d) { atomicAdd(&s_acc[h], pp[j]); break; }
                h = (h + 1) & (TSIZE - 1);
            }
        }
    }
    __syncthreads();

    // ---- epilogue: 10 threads, one option each ----
    if (tid < O) {
        float sum = 0.0f;
        float cnt = 0.0f;
        #pragma unroll
        for (int w = 0; w < W; w++) {
            const int key = opt[tid * W + w];
            unsigned h = hash_key(key);
            while (s_key[h] != key) h = (h + 1) & (TSIZE - 1);  // guaranteed present
            sum += s_acc[h];
            if (key != 0) cnt += 1.0f;
        }
        out[b * O + tid] = sum / cnt;
    }
}

extern "C" void kernel_launch(void* const* d_in, const int* in_sizes, int n_in,
                              void* d_out, int out_size) {
    const int*   doc_idx  = (const int*)d_in[0];     // (B, L) int32 (JAX-downgraded int64)
    const float* doc_prob = (const float*)d_in[1];   // (B, L) float32
    const int*   options  = (const int*)d_in[2];     // (B, O, W) int32
    float*       out      = (float*)d_out;           // (B, O) float32

    option_attention_sum_kernel<<<B, THREADS>>>(doc_idx, doc_prob, options, out);
}

// round 3
// speedup vs baseline: 1.0332x; 1.0332x over previous
#include <cuda_runtime.h>
#include <cuda_bf16.h>
#include <cstdint>

// OptionAttentionSum: out[b,o] = (sum_w sum_l [doc[b,l]==opt[b,o,w]] * prob[b,l]) / #nonzero words
//
// R3 strategy: split each batch row into S=4 segments (grid 512 CTAs, 256 thr) to
// fix the R2 latency-hiding failure (occ 22%, 20 idle SMs). Each CTA builds a
// 2048-slot hash table (load factor 0.024 -> ~branchless single probe), streams
// its 1024-element segment with one int4+float4 load per thread, writes per-option
// partial sums to a __device__ scratch. A tiny second kernel reduces S partials
// and divides by the nonzero-word count. Scratch is fully overwritten every call
// (deterministic, no zeroing, no atomics on global).

static constexpr int B = 128;
static constexpr int L = 4096;
static constexpr int O = 10;
static constexpr int W = 5;
static constexpr int OW = O * W;          // 50
static constexpr int S = 4;               // segments per batch row
static constexpr int SEG = L / S;         // 1024 elements per segment
static constexpr int THREADS = 256;       // SEG/4 vectors -> 1 int4 per thread
static constexpr int TSIZE = 2048;        // hash slots (power of 2), load ~0.024
static constexpr int KEMPTY = (int)0x80000000;  // impossible key (values in [0, 50000))

__device__ float g_partial[B * S * O];    // per-(batch,segment) partial sums

__device__ __forceinline__ unsigned hash_key(int key) {
    return ((unsigned)key * 2654435761u) >> (32 - 11);   // top 11 bits -> [0,2048)
}

__global__ __launch_bounds__(THREADS)
void oas_partial_kernel(const int* __restrict__ doc_idx,
                        const float* __restrict__ doc_prob,
                        const int* __restrict__ options) {
    __shared__ int   s_key[TSIZE];
    __shared__ float s_acc[TSIZE];

    const int bx  = blockIdx.x;
    const int b   = bx >> 2;        // batch
    const int seg = bx & (S - 1);   // segment within the row
    const int tid = threadIdx.x;

    // ---- init table: 2048/256 = 8 stores per thread ----
    #pragma unroll
    for (int i = tid; i < TSIZE; i += THREADS) {
        s_key[i] = KEMPTY;
        s_acc[i] = 0.0f;
    }
    __syncthreads();

    // ---- insert the (<=50) option words ----
    const int* opt = options + b * OW;
    if (tid < OW) {
        const int key = opt[tid];
        unsigned h = hash_key(key);
        while (true) {
            int old = atomicCAS(&s_key[h], KEMPTY, key);
            if (old == KEMPTY || old == key) break;
            h = (h + 1) & (TSIZE - 1);
        }
    }
    __syncthreads();

    // ---- stream this segment: exactly one int4 + float4 per thread ----
    const int base = b * L + seg * SEG;
    const int4   d4 = reinterpret_cast<const int4*>(doc_idx + base)[tid];
    const float4 p4 = reinterpret_cast<const float4*>(doc_prob + base)[tid];

    const int   dk[4] = {d4.x, d4.y, d4.z, d4.w};
    const float pp[4] = {p4.x, p4.y, p4.z, p4.w};

    #pragma unroll
    for (int j = 0; j < 4; j++) {
        const int d = dk[j];
        unsigned h = hash_key(d);
        const int k0 = s_key[h];
        if (k0 == d) {
            atomicAdd(&s_acc[h], pp[j]);          // hit on first probe (~97.6% of occupied)
        } else if (k0 != KEMPTY) {                // rare: collided slot, walk the cluster
            h = (h + 1) & (TSIZE - 1);
            while (true) {
                const int k = s_key[h];
                if (k == KEMPTY) break;
                if (k == d) { atomicAdd(&s_acc[h], pp[j]); break; }
                h = (h + 1) & (TSIZE - 1);
            }
        }
        // k0 == KEMPTY: miss, nothing to do (common case: ~95.9% of all elements)
    }
    __syncthreads();

    // ---- per-option partial sums for this segment ----
    if (tid < O) {
        float sum = 0.0f;
        #pragma unroll
        for (int w = 0; w < W; w++) {
            const int key = opt[tid * W + w];
            unsigned h = hash_key(key);
            while (s_key[h] != key) h = (h + 1) & (TSIZE - 1);  // guaranteed present
            sum += s_acc[h];
        }
        g_partial[(b * S + seg) * O + tid] = sum;
    }
}

__global__ void oas_reduce_kernel(const int* __restrict__ options,
                                  float* __restrict__ out) {
    const int i = blockIdx.x * blockDim.x + threadIdx.x;   // 0 .. B*O-1
    if (i >= B * O) return;
    const int b = i / O;
    const int o = i % O;

    float sum = 0.0f;
    #pragma unroll
    for (int s = 0; s < S; s++) {
        sum += g_partial[(b * S + s) * O + o];
    }

    float cnt = 0.0f;
    #pragma unroll
    for (int w = 0; w < W; w++) {
        if (options[b * OW + o * W + w] != 0) cnt += 1.0f;
    }
    out[i] = sum / cnt;
}

extern "C" void kernel_launch(void* const* d_in, const int* in_sizes, int n_in,
                              void* d_out, int out_size) {
    const int*   doc_idx  = (const int*)d_in[0];     // (B, L) int32 (JAX-downgraded int64)
    const float* doc_prob = (const float*)d_in[1];   // (B, L) float32
    const int*   options  = (const int*)d_in[2];     // (B, O, W) int32
    float*       out      = (float*)d_out;           // (B, O) float32

    oas_partial_kernel<<<B * S, THREADS>>>(doc_idx, doc_prob, options);
    oas_reduce_kernel<<<(B * O + 255) / 256, 256>>>(options, out);
}